// round 4
// baseline (speedup 1.0000x reference)
#include <cuda_runtime.h>
#include <cstdint>

#define NCELLS 131072
#define HIDD   256
#define OUTD   128
#define MC     32
#define NBLK   (NCELLS/MC)   // 4096
#define FS     16384         // cells per faction
#define DC     4096          // debate count

// ---------------- scratch (device globals, no allocation) ----------------
__device__ float d_hp[NCELLS*HIDD];        // post-payoff clamped hidden
__device__ float d_pfsum[NBLK*HIDD];       // per-block faction partial sums
__device__ float d_pexpout[NBLK*OUTD];     // per-block sum exp(t)*out
__device__ float d_pexpsum[NBLK];
__device__ float d_ptsum[NBLK];
__device__ float d_xa[OUTD];               // a_b1 + x @ a_w1[:, :128]^T
__device__ float d_xg[OUTD];
__device__ float d_Sf[8*HIDD];
__device__ float d_Df[8*HIDD];
__device__ float d_eor[OUTD];
__device__ float d_es;
__device__ float d_ts;
__device__ float d_fmean[8*HIDD];
__device__ float d_go[HIDD];
__device__ float d_gmean[HIDD];

// ---------------- smem layout (floats) ----------------
#define SM_HS   0                  // 32x256 hidden tile
#define SM_W    8192               // weight staging (max 16*192=3072 floats)
#define SM_WA   8192               // 16x132
#define SM_WG   (8192+2112)        // 16x132
#define SM_A1   12416              // 32x128 relu(a1)
#define SM_G1   16512              // 32x128 relu(g1)
#define SM_OUT  20608              // 32x128 out (= mem_in[:, :128])
#define SM_T    24704              // 32 tension
#define SM_E    24736              // 32 exp(tension)
#define SM_TOT  24768
#define SM_HP   SM_A1              // alias: 32x256 new_h tile (over A1+G1)

// ================= K0: fold x into stage-1 bias =================
__global__ void k0(const float* __restrict__ x,
                   const float* __restrict__ aw1, const float* __restrict__ ab1,
                   const float* __restrict__ gw1, const float* __restrict__ gb1) {
    int t = threadIdx.x;
    if (t < 128) {
        float s = ab1[t];
        const float* w = aw1 + t*384;
        for (int k = 0; k < 128; k++) s = fmaf(x[k], w[k], s);
        d_xa[t] = s;
    } else {
        int j = t - 128;
        float s = gb1[j];
        const float* w = gw1 + j*384;
        for (int k = 0; k < 128; k++) s = fmaf(x[k], w[k], s);
        d_xg[j] = s;
    }
}

// ================= KA: fused per-cell pipeline =================
__global__ __launch_bounds__(256, 2)
void kA(const float* __restrict__ hiddens, const float* __restrict__ payoffs,
        const float* __restrict__ aw1, const float* __restrict__ gw1,
        const float* __restrict__ aw2, const float* __restrict__ ab2,
        const float* __restrict__ gw2, const float* __restrict__ gb2,
        const float* __restrict__ wih, const float* __restrict__ whh,
        const float* __restrict__ bih, const float* __restrict__ bhh) {
    extern __shared__ float sm[];
    const int t = threadIdx.x, b = blockIdx.x;
    const int cell0 = b * MC;

    // load 32x256 hidden tile (coalesced float4)
    {
        const float4* hg = (const float4*)(hiddens + (size_t)cell0 * HIDD);
        float4* hs4 = (float4*)(sm + SM_HS);
        #pragma unroll
        for (int e = t; e < (MC*HIDD)/4; e += 256) hs4[e] = hg[e];
    }

    const int jg = t & 31, cg = t >> 5;
    const int j0 = jg * 4, c0 = cg * 4;

    // ---------- stage 1: a1 = relu(comb @ a_w1^T + b1), g1 likewise ----------
    float acc_a[4][4], acc_g[4][4];
    {
        float4 xa4 = *(const float4*)(d_xa + j0);
        float4 xg4 = *(const float4*)(d_xg + j0);
        #pragma unroll
        for (int ci = 0; ci < 4; ci++) {
            acc_a[ci][0] = xa4.x; acc_a[ci][1] = xa4.y; acc_a[ci][2] = xa4.z; acc_a[ci][3] = xa4.w;
            acc_g[ci][0] = xg4.x; acc_g[ci][1] = xg4.y; acc_g[ci][2] = xg4.z; acc_g[ci][3] = xg4.w;
        }
    }
    for (int k0c = 0; k0c < 256; k0c += 16) {
        __syncthreads();
        #pragma unroll
        for (int e = t; e < 2048; e += 256) {
            int kk = e & 15, j = e >> 4;
            sm[SM_WA + kk*132 + j] = aw1[j*384 + 128 + k0c + kk];
            sm[SM_WG + kk*132 + j] = gw1[j*384 + 128 + k0c + kk];
        }
        __syncthreads();
        #pragma unroll
        for (int kk = 0; kk < 16; kk++) {
            float4 wa = *(float4*)(sm + SM_WA + kk*132 + j0);
            float4 wg = *(float4*)(sm + SM_WG + kk*132 + j0);
            #pragma unroll
            for (int ci = 0; ci < 4; ci++) {
                float hv = sm[SM_HS + (c0+ci)*256 + k0c + kk];
                acc_a[ci][0] = fmaf(hv, wa.x, acc_a[ci][0]);
                acc_a[ci][1] = fmaf(hv, wa.y, acc_a[ci][1]);
                acc_a[ci][2] = fmaf(hv, wa.z, acc_a[ci][2]);
                acc_a[ci][3] = fmaf(hv, wa.w, acc_a[ci][3]);
                acc_g[ci][0] = fmaf(hv, wg.x, acc_g[ci][0]);
                acc_g[ci][1] = fmaf(hv, wg.y, acc_g[ci][1]);
                acc_g[ci][2] = fmaf(hv, wg.z, acc_g[ci][2]);
                acc_g[ci][3] = fmaf(hv, wg.w, acc_g[ci][3]);
            }
        }
    }
    __syncthreads();
    #pragma unroll
    for (int ci = 0; ci < 4; ci++) {
        float4 va, vg;
        va.x = fmaxf(acc_a[ci][0], 0.f); va.y = fmaxf(acc_a[ci][1], 0.f);
        va.z = fmaxf(acc_a[ci][2], 0.f); va.w = fmaxf(acc_a[ci][3], 0.f);
        vg.x = fmaxf(acc_g[ci][0], 0.f); vg.y = fmaxf(acc_g[ci][1], 0.f);
        vg.z = fmaxf(acc_g[ci][2], 0.f); vg.w = fmaxf(acc_g[ci][3], 0.f);
        *(float4*)(sm + SM_A1 + (c0+ci)*128 + j0) = va;
        *(float4*)(sm + SM_G1 + (c0+ci)*128 + j0) = vg;
    }

    // ---------- stage 2: out = (a1@a_w2^T + ab2) - (g1@g_w2^T + gb2) ----------
    float acc[4][4];
    {
        float4 ba = *(const float4*)(ab2 + j0);
        float4 bg = *(const float4*)(gb2 + j0);
        #pragma unroll
        for (int ci = 0; ci < 4; ci++) {
            acc[ci][0] = ba.x - bg.x; acc[ci][1] = ba.y - bg.y;
            acc[ci][2] = ba.z - bg.z; acc[ci][3] = ba.w - bg.w;
        }
    }
    for (int k0c = 0; k0c < 128; k0c += 16) {
        __syncthreads();
        #pragma unroll
        for (int e = t; e < 2048; e += 256) {
            int kk = e & 15, j = e >> 4;
            sm[SM_WA + kk*132 + j] = aw2[j*128 + k0c + kk];
            sm[SM_WG + kk*132 + j] = gw2[j*128 + k0c + kk];
        }
        __syncthreads();
        #pragma unroll
        for (int kk = 0; kk < 16; kk++) {
            float4 wa = *(float4*)(sm + SM_WA + kk*132 + j0);
            float4 wg = *(float4*)(sm + SM_WG + kk*132 + j0);
            #pragma unroll
            for (int ci = 0; ci < 4; ci++) {
                float av = sm[SM_A1 + (c0+ci)*128 + k0c + kk];
                float gv = sm[SM_G1 + (c0+ci)*128 + k0c + kk];
                acc[ci][0] = fmaf(av, wa.x, acc[ci][0]); acc[ci][0] = fmaf(-gv, wg.x, acc[ci][0]);
                acc[ci][1] = fmaf(av, wa.y, acc[ci][1]); acc[ci][1] = fmaf(-gv, wg.y, acc[ci][1]);
                acc[ci][2] = fmaf(av, wa.z, acc[ci][2]); acc[ci][2] = fmaf(-gv, wg.z, acc[ci][2]);
                acc[ci][3] = fmaf(av, wa.w, acc[ci][3]); acc[ci][3] = fmaf(-gv, wg.w, acc[ci][3]);
            }
        }
    }
    __syncthreads();
    #pragma unroll
    for (int ci = 0; ci < 4; ci++) {
        float4 vo; vo.x = acc[ci][0]; vo.y = acc[ci][1]; vo.z = acc[ci][2]; vo.w = acc[ci][3];
        *(float4*)(sm + SM_OUT + (c0+ci)*128 + j0) = vo;
    }
    __syncthreads();

    // tension + exp (deterministic ordered sums)
    if (t < 32) {
        float s = 0.f;
        const float* o = sm + SM_OUT + t*128;
        for (int j = 0; j < 128; j++) { float v = o[j]; s = fmaf(v, v, s); }
        s *= (1.0f/128.0f);
        sm[SM_T + t] = s;
        sm[SM_E + t] = expf(s);
    }
    __syncthreads();
    if (t < 128) {
        float s = 0.f;
        for (int c = 0; c < 32; c++) s = fmaf(sm[SM_E + c], sm[SM_OUT + c*128 + t], s);
        d_pexpout[b*128 + t] = s;
    } else if (t == 128) {
        float s = 0.f; for (int c = 0; c < 32; c++) s += sm[SM_E + c];
        d_pexpsum[b] = s;
    } else if (t == 129) {
        float s = 0.f; for (int c = 0; c < 32; c++) s += sm[SM_T + c];
        d_ptsum[b] = s;
    }

    // ---------- stage 3: fused GRU ----------
    float pay[4];
    #pragma unroll
    for (int ci = 0; ci < 4; ci++) pay[ci] = payoffs[cell0 + c0 + ci];
    const int dd0 = (t & 31) * 2;

    for (int dc0 = 0; dc0 < 256; dc0 += 64) {
        const int dgl0 = dc0 + dd0;
        float ar[4][2], az[4][2], ain[4][2], ahn[4][2];
        #pragma unroll
        for (int dj = 0; dj < 2; dj++) {
            float br  = __ldg(&bih[dgl0+dj])     + __ldg(&bhh[dgl0+dj]);
            float bz  = __ldg(&bih[256+dgl0+dj]) + __ldg(&bhh[256+dgl0+dj]);
            float bni = __ldg(&bih[512+dgl0+dj]);
            float bnh = __ldg(&bhh[512+dgl0+dj]);
            #pragma unroll
            for (int ci = 0; ci < 4; ci++) { ar[ci][dj]=br; az[ci][dj]=bz; ain[ci][dj]=bni; ahn[ci][dj]=bnh; }
        }
        // W_ih part, K = 0..127 (mem_in[:, :128] = out)
        for (int k0c = 0; k0c < 128; k0c += 16) {
            __syncthreads();
            #pragma unroll
            for (int e = t; e < 3072; e += 256) {
                int kk = e & 15, col = e >> 4;
                int g = col >> 6, dd = col & 63;
                sm[SM_W + kk*192 + col] = wih[(g*256 + dc0 + dd)*129 + k0c + kk];
            }
            __syncthreads();
            #pragma unroll
            for (int kk = 0; kk < 16; kk++) {
                float2 wr = *(float2*)(sm + SM_W + kk*192 + dd0);
                float2 wz = *(float2*)(sm + SM_W + kk*192 + 64 + dd0);
                float2 wn = *(float2*)(sm + SM_W + kk*192 + 128 + dd0);
                #pragma unroll
                for (int ci = 0; ci < 4; ci++) {
                    float m = sm[SM_OUT + (c0+ci)*128 + k0c + kk];
                    ar[ci][0]  = fmaf(m, wr.x, ar[ci][0]);  ar[ci][1]  = fmaf(m, wr.y, ar[ci][1]);
                    az[ci][0]  = fmaf(m, wz.x, az[ci][0]);  az[ci][1]  = fmaf(m, wz.y, az[ci][1]);
                    ain[ci][0] = fmaf(m, wn.x, ain[ci][0]); ain[ci][1] = fmaf(m, wn.y, ain[ci][1]);
                }
            }
        }
        // tension column (k = 128)
        {
            float wtr[2], wtz[2], wtn[2];
            #pragma unroll
            for (int dj = 0; dj < 2; dj++) {
                wtr[dj] = __ldg(&wih[(dgl0+dj)*129 + 128]);
                wtz[dj] = __ldg(&wih[(256+dgl0+dj)*129 + 128]);
                wtn[dj] = __ldg(&wih[(512+dgl0+dj)*129 + 128]);
            }
            #pragma unroll
            for (int ci = 0; ci < 4; ci++) {
                float tv = sm[SM_T + c0 + ci];
                #pragma unroll
                for (int dj = 0; dj < 2; dj++) {
                    ar[ci][dj]  = fmaf(tv, wtr[dj], ar[ci][dj]);
                    az[ci][dj]  = fmaf(tv, wtz[dj], az[ci][dj]);
                    ain[ci][dj] = fmaf(tv, wtn[dj], ain[ci][dj]);
                }
            }
        }
        // W_hh part, K = 0..255
        for (int k0c = 0; k0c < 256; k0c += 16) {
            __syncthreads();
            #pragma unroll
            for (int e = t; e < 3072; e += 256) {
                int kk = e & 15, col = e >> 4;
                int g = col >> 6, dd = col & 63;
                sm[SM_W + kk*192 + col] = whh[(g*256 + dc0 + dd)*256 + k0c + kk];
            }
            __syncthreads();
            #pragma unroll
            for (int kk = 0; kk < 16; kk++) {
                float2 ur = *(float2*)(sm + SM_W + kk*192 + dd0);
                float2 uz = *(float2*)(sm + SM_W + kk*192 + 64 + dd0);
                float2 un = *(float2*)(sm + SM_W + kk*192 + 128 + dd0);
                #pragma unroll
                for (int ci = 0; ci < 4; ci++) {
                    float m = sm[SM_HS + (c0+ci)*256 + k0c + kk];
                    ar[ci][0]  = fmaf(m, ur.x, ar[ci][0]);  ar[ci][1]  = fmaf(m, ur.y, ar[ci][1]);
                    az[ci][0]  = fmaf(m, uz.x, az[ci][0]);  az[ci][1]  = fmaf(m, uz.y, az[ci][1]);
                    ahn[ci][0] = fmaf(m, un.x, ahn[ci][0]); ahn[ci][1] = fmaf(m, un.y, ahn[ci][1]);
                }
            }
        }
        // gates + payoff clamp + write
        #pragma unroll
        for (int ci = 0; ci < 4; ci++) {
            float scale = fmaf(0.02f, pay[ci], 0.9f);
            #pragma unroll
            for (int dj = 0; dj < 2; dj++) {
                float r  = 1.0f / (1.0f + expf(-ar[ci][dj]));
                float z  = 1.0f / (1.0f + expf(-az[ci][dj]));
                float nn = tanhf(fmaf(r, ahn[ci][dj], ain[ci][dj]));
                float h  = sm[SM_HS + (c0+ci)*256 + dgl0 + dj];
                float v  = (1.0f - z) * nn + z * h;
                v *= scale;
                v = fminf(10.0f, fmaxf(-10.0f, v));
                d_hp[(size_t)(cell0 + c0 + ci)*256 + dgl0 + dj] = v;
                sm[SM_HP + (c0+ci)*256 + dgl0 + dj] = v;
            }
        }
    }
    __syncthreads();
    // per-block faction partial sums (deterministic order)
    {
        float s = 0.f;
        for (int c = 0; c < 32; c++) s += sm[SM_HP + c*256 + t];
        d_pfsum[b*256 + t] = s;
    }
}

// ================= KB1: deterministic reductions =================
__global__ void kB1() {
    int tid = blockIdx.x * blockDim.x + threadIdx.x;
    if (tid < 2048) {
        int f = tid >> 8, d = tid & 255;
        float S = 0.f, D = 0.f;
        const float* p = d_pfsum + (size_t)(f*512)*256 + d;
        for (int b2 = 0; b2 < 512; b2++) {
            float v = p[(size_t)b2*256];
            S += v;
            if (b2 < 128) D += v;   // first DC=4096 cells of faction = first 128 blocks
        }
        d_Sf[tid] = S; d_Df[tid] = D;
    } else if (tid < 2176) {
        int j = tid - 2048; float s = 0.f;
        for (int b2 = 0; b2 < NBLK; b2++) s += d_pexpout[b2*128 + j];
        d_eor[j] = s;
    } else if (tid == 2176) {
        float s = 0.f; for (int b2 = 0; b2 < NBLK; b2++) s += d_pexpsum[b2];
        d_es = s;
    } else if (tid == 2177) {
        float s = 0.f; for (int b2 = 0; b2 < NBLK; b2++) s += d_ptsum[b2];
        d_ts = s;
    }
}

// ================= KB2: stats + pred + avg_tension =================
__global__ void kB2(const float* __restrict__ head_w, const float* __restrict__ head_b,
                    const int* __restrict__ stepp, float* __restrict__ out) {
    int t = threadIdx.x;
    int step = *stepp;
    if (t < 256) {
        float Sfv[8];
        #pragma unroll
        for (int f = 0; f < 8; f++) Sfv[f] = d_Sf[f*256 + t];
        float go = 0.f;
        #pragma unroll
        for (int f = 0; f < 8; f++) go += Sfv[f] * (1.0f/16384.0f);
        go *= 0.125f;
        d_go[t] = go;
        float gsum = 0.f;
        #pragma unroll
        for (int f = 0; f < 8; f++) {
            float fm = Sfv[f] * (1.0f/16384.0f);
            d_fmean[f*256 + t] = fm;
            float Tf = Sfv[f];
            if (step > 5) {
                float D = d_Df[f*256 + t];
                Tf += 0.15f * (4096.0f*go - 0.85f*D - 4096.0f*0.15f*fm);
            }
            gsum += Tf;
        }
        d_gmean[t] = gsum * (1.0f/131072.0f);
    }
    if (t < 128) {
        float inv = 1.0f / d_es;
        float s = head_b[t];
        const float* hw = head_w + t*128;
        for (int j = 0; j < 128; j++) s = fmaf(d_eor[j]*inv, hw[j], s);
        out[t] = s;
    }
    if (t == 0) out[128] = d_ts * (1.0f/131072.0f);
}

// ================= threefry + XLA erf_inv for exact JAX noise =================
// Partitionable threefry (JAX >= 0.4.30 default): per flat element i,
// (o0,o1) = threefry2x32(key=(0,42), counts=(hi32(i), lo32(i))); bits = o0 ^ o1.
__device__ __forceinline__ uint32_t threefry_bits(uint32_t x0, uint32_t x1) {
    const uint32_t ks0 = 0u, ks1 = 42u, ks2 = 0x1BD11BF0u; // 0^42^0x1BD11BDA
    x0 += ks0; x1 += ks1;
#define RND(R) { x0 += x1; x1 = (x1 << R) | (x1 >> (32 - R)); x1 ^= x0; }
    RND(13) RND(15) RND(26) RND(6)   x0 += ks1; x1 += ks2 + 1u;
    RND(17) RND(29) RND(16) RND(24)  x0 += ks2; x1 += ks0 + 2u;
    RND(13) RND(15) RND(26) RND(6)   x0 += ks0; x1 += ks1 + 3u;
    RND(17) RND(29) RND(16) RND(24)  x0 += ks1; x1 += ks2 + 4u;
    RND(13) RND(15) RND(26) RND(6)   x0 += ks2; x1 += ks0 + 5u;
#undef RND
    return x0 ^ x1;
}

__device__ __forceinline__ float erfinv_xla(float x) {
    float w = -log1pf(-x * x);
    float p;
    if (w < 5.0f) {
        w -= 2.5f;
        p = 2.81022636e-08f;
        p = fmaf(p, w, 3.43273939e-07f);
        p = fmaf(p, w, -3.5233877e-06f);
        p = fmaf(p, w, -4.39150654e-06f);
        p = fmaf(p, w, 0.00021858087f);
        p = fmaf(p, w, -0.00125372503f);
        p = fmaf(p, w, -0.00417768164f);
        p = fmaf(p, w, 0.246640727f);
        p = fmaf(p, w, 1.50140941f);
    } else {
        w = sqrtf(w) - 3.0f;
        p = -0.000200214257f;
        p = fmaf(p, w, 0.000100950558f);
        p = fmaf(p, w, 0.00134934322f);
        p = fmaf(p, w, -0.00367342844f);
        p = fmaf(p, w, 0.00573950773f);
        p = fmaf(p, w, -0.0076224613f);
        p = fmaf(p, w, 0.00943887047f);
        p = fmaf(p, w, 1.00167406f);
        p = fmaf(p, w, 2.83297682f);
    }
    return p * x;
}

__device__ __forceinline__ float bits_to_normal(uint32_t bits) {
    float u01 = __uint_as_float((bits >> 9) | 0x3f800000u) - 1.0f;   // [0,1)
    float u = u01 * 2.0f + (-0.99999994f);                            // jax uniform(lo,hi)
    u = fmaxf(-0.99999994f, u);
    return 1.4142135623730951f * erfinv_xla(u);
}

// ================= KC: sync/debate/pull/noise/clamp =================
__global__ void kC(const int* __restrict__ lact, const int* __restrict__ stepp,
                   float* __restrict__ out) {
    const int cell = blockIdx.x;       // 0..65535
    const int d = threadIdx.x;         // 0..255
    const int step = *stepp;
    uint32_t m = (uint32_t)cell * 256u + (uint32_t)d;
    // partitionable threefry: counts64 = flat index, hi word = 0 for both halves
    float n0 = bits_to_normal(threefry_bits(0u, m));
    float n1 = bits_to_normal(threefry_bits(0u, m + 16777216u));
    const float gm = d_gmean[d];
    const float go = d_go[d];

    #pragma unroll
    for (int half = 0; half < 2; half++) {
        int c = cell + half * 65536;
        float n = half ? n1 : n0;
        float v = d_hp[(size_t)c*256 + d];
        int f = c >> 14;
        v = 0.85f * v + 0.15f * d_fmean[f*256 + d];
        if (step > 5 && (c & 16383) < DC) v = 0.85f * v + 0.15f * go;
        float coop = (float)lact[c];
        v += 0.05f * coop * (gm - v);
        v += 0.02f * (1.0f - coop) * n;
        v = fminf(10.0f, fmaxf(-10.0f, v));
        out[129 + (size_t)c*256 + d] = v;
    }
}

// ================= launch =================
extern "C" void kernel_launch(void* const* d_in, const int* in_sizes, int n_in,
                              void* d_out, int out_size) {
    const float* x        = (const float*)d_in[0];
    const float* payoffs  = (const float*)d_in[1];
    const int*   last     = (const int*)d_in[2];
    const int*   step     = (const int*)d_in[3];
    const float* hiddens  = (const float*)d_in[4];
    const float* a_w1     = (const float*)d_in[5];
    const float* a_b1     = (const float*)d_in[6];
    const float* a_w2     = (const float*)d_in[7];
    const float* a_b2     = (const float*)d_in[8];
    const float* g_w1     = (const float*)d_in[9];
    const float* g_b1     = (const float*)d_in[10];
    const float* g_w2     = (const float*)d_in[11];
    const float* g_b2     = (const float*)d_in[12];
    const float* gru_wih  = (const float*)d_in[13];
    const float* gru_whh  = (const float*)d_in[14];
    const float* gru_bih  = (const float*)d_in[15];
    const float* gru_bhh  = (const float*)d_in[16];
    const float* head_w   = (const float*)d_in[17];
    const float* head_b   = (const float*)d_in[18];
    float* out = (float*)d_out;

    cudaFuncSetAttribute(kA, cudaFuncAttributeMaxDynamicSharedMemorySize, SM_TOT * 4);

    k0<<<1, 256>>>(x, a_w1, a_b1, g_w1, g_b1);
    kA<<<NBLK, 256, SM_TOT * 4>>>(hiddens, payoffs, a_w1, g_w1, a_w2, a_b2, g_w2, g_b2,
                                  gru_wih, gru_whh, gru_bih, gru_bhh);
    kB1<<<18, 128>>>();
    kB2<<<1, 256>>>(head_w, head_b, step, out);
    kC<<<65536, 256>>>(last, step, out);
}

// round 5
// speedup vs baseline: 2.6296x; 2.6296x over previous
#include <cuda_runtime.h>
#include <cstdint>

#define NCELLS 131072
#define MC     64
#define NBLK   (NCELLS/MC)   // 2048
#define DC     4096

// ---------------- device scratch ----------------
__device__ __align__(16) float d_W1p[32*32*64];      // stage1 B frags
__device__ __align__(16) float d_W2p[32*16*64];      // stage2 B frags
__device__ __align__(16) float d_Wgp[4*49*4*8*64];   // GRU B frags
__device__ float d_xa[128], d_xg[128], d_b2d[128];
__device__ float d_hp[NCELLS*256];
__device__ float d_pfsum[NBLK*256];
__device__ float d_pexpout[NBLK*128];
__device__ float d_pexpsum[NBLK], d_ptsum[NBLK];
__device__ float d_Sf[8*256], d_Df[8*256], d_eor[128], d_es, d_ts;
__device__ float d_fmean[8*256], d_go[256], d_gmean[256];

// ---------------- smem layout (float words) ----------------
#define A1S 260
#define A3S 148
#define SA1 0          // h tile 64x260 (also GRU K-tail A)
#define SA2 16640      // [a1|g1] 64x260, reused for new_h
#define SA3 33280      // [out|tension|1|0s] 64x148
#define ST  42752
#define SE  42816
#define SPAY 42880
#define SMW 42944      // words -> 171776 bytes

__device__ __forceinline__ float rna(float x){
    float r; asm("cvt.rna.tf32.f32 %0, %1;" : "=f"(r) : "f"(x)); return r;
}
__device__ __forceinline__ void mma8(float* c, const uint32_t* a, float2 b){
    asm volatile(
        "mma.sync.aligned.m16n8k8.row.col.f32.tf32.tf32.f32 "
        "{%0,%1,%2,%3}, {%4,%5,%6,%7}, {%8,%9}, {%0,%1,%2,%3};"
        : "+f"(c[0]), "+f"(c[1]), "+f"(c[2]), "+f"(c[3])
        : "r"(a[0]), "r"(a[1]), "r"(a[2]), "r"(a[3]),
          "r"(__float_as_uint(b.x)), "r"(__float_as_uint(b.y)));
}

// ================= kPrep: permute weights into B-fragment layout =================
__global__ void kPrep(const float* __restrict__ x,
                      const float* __restrict__ aw1, const float* __restrict__ ab1,
                      const float* __restrict__ gw1, const float* __restrict__ gb1,
                      const float* __restrict__ aw2, const float* __restrict__ ab2,
                      const float* __restrict__ gw2, const float* __restrict__ gb2,
                      const float* __restrict__ wih, const float* __restrict__ whh,
                      const float* __restrict__ bih, const float* __restrict__ bhh) {
    int tid = blockIdx.x*blockDim.x + threadIdx.x;
    int nth = gridDim.x*blockDim.x;
    for (int i = tid; i < 32*32*64; i += nth){
        int q=i&1, l=(i>>1)&31, nb=(i>>6)&31, ks=i>>11;
        int j=(nb&15)*8+(l>>2), k=ks*8+(l&3)+q*4;
        const float* w = (nb<16)? aw1 : gw1;
        d_W1p[i] = rna(w[j*384 + 128 + k]);
    }
    for (int i = tid; i < 32*16*64; i += nth){
        int q=i&1, l=(i>>1)&31, nb=(i>>6)&15, ks=i>>10;
        int j=nb*8+(l>>2), k=ks*8+(l&3)+q*4;
        float v = (k<128)? aw2[j*128+k] : -gw2[j*128+(k-128)];
        d_W2p[i] = rna(v);
    }
    // GRU: K=[out 0..127 | tension 128 | ones 129 | 0 130..135 | h 136..391]
    for (int i = tid; i < 4*49*4*8*64; i += nth){
        int q=i&1, l=(i>>1)&31, w8=(i>>6)&7, g=(i>>9)&3, rest=i>>11;
        int ks=rest%49, slice=rest/49;
        int d=(slice*8+w8)*8+(l>>2);
        int k=ks*8+(l&3)+q*4;
        float v = 0.f;
        if (g==0){
            if (k<129) v = wih[d*129+k];
            else if (k==129) v = bih[d]+bhh[d];
            else if (k>=136) v = whh[d*256+k-136];
        } else if (g==1){
            int r = 256+d;
            if (k<129) v = wih[r*129+k];
            else if (k==129) v = bih[r]+bhh[r];
            else if (k>=136) v = whh[r*256+k-136];
        } else if (g==2){
            int r = 512+d;
            if (k<129) v = wih[r*129+k];
            else if (k==129) v = bih[r];
        } else {
            int r = 512+d;
            if (k==129) v = bhh[r];
            else if (k>=136) v = whh[r*256+k-136];
        }
        d_Wgp[i] = rna(v);
    }
    if (tid < 128){
        d_b2d[tid] = ab2[tid] - gb2[tid];
        float s = ab1[tid];
        const float* w = aw1 + tid*384;
        for (int k = 0; k < 128; k++) s = fmaf(x[k], w[k], s);
        d_xa[tid] = s;
        s = gb1[tid];
        w = gw1 + tid*384;
        for (int k = 0; k < 128; k++) s = fmaf(x[k], w[k], s);
        d_xg[tid] = s;
    }
}

// ================= kA: tensor-core fused pipeline =================
__global__ __launch_bounds__(256,1)
void kA(const float* __restrict__ hiddens, const float* __restrict__ payoffs){
    extern __shared__ float sm[];
    const int t = threadIdx.x, b = blockIdx.x, cell0 = b*MC;
    const int warp = t>>5, lane = t&31, gid = lane>>2, tig = lane&3;

    for (int e = t; e < 64*64; e += 256){
        int row = e>>6, c4 = e&63;
        float4 v = ((const float4*)hiddens)[(size_t)(cell0+row)*64 + c4];
        *(float4*)(sm + SA1 + row*A1S + c4*4) = v;
    }
    if (t < 64){
        sm[SPAY+t] = payoffs[cell0+t];
        float* r3 = sm + SA3 + t*A3S;
        r3[129] = 1.f;
        #pragma unroll
        for (int c = 130; c < 136; c++) r3[c] = 0.f;
    }
    __syncthreads();

    // ---------- stage 1 ----------
    float acc[4][4][4];
    #pragma unroll
    for (int nbI = 0; nbI < 4; nbI++){
        int nb = warp + nbI*8;
        const float* xv = ((nb<16)? d_xa : d_xg) + (nb&15)*8 + 2*tig;
        float i0 = xv[0], i1 = xv[1];
        #pragma unroll
        for (int mb = 0; mb < 4; mb++){
            acc[nbI][mb][0]=i0; acc[nbI][mb][1]=i1; acc[nbI][mb][2]=i0; acc[nbI][mb][3]=i1;
        }
    }
    #pragma unroll 4
    for (int ks = 0; ks < 32; ks++){
        uint32_t af[4][4];
        #pragma unroll
        for (int mb = 0; mb < 4; mb++){
            const float* ap = sm + SA1 + (mb*16+gid)*A1S + ks*8 + tig;
            af[mb][0]=__float_as_uint(ap[0]);   af[mb][1]=__float_as_uint(ap[8*A1S]);
            af[mb][2]=__float_as_uint(ap[4]);   af[mb][3]=__float_as_uint(ap[8*A1S+4]);
        }
        #pragma unroll
        for (int nbI = 0; nbI < 4; nbI++){
            float2 bf = __ldg((const float2*)(d_W1p + (ks*32 + warp + nbI*8)*64 + lane*2));
            #pragma unroll
            for (int mb = 0; mb < 4; mb++) mma8(acc[nbI][mb], af[mb], bf);
        }
    }
    __syncthreads();
    #pragma unroll
    for (int nbI = 0; nbI < 4; nbI++){
        int col = (warp + nbI*8)*8 + 2*tig;
        #pragma unroll
        for (int mb = 0; mb < 4; mb++){
            int row = mb*16 + gid;
            sm[SA2+row*A1S+col]       = fmaxf(acc[nbI][mb][0], 0.f);
            sm[SA2+row*A1S+col+1]     = fmaxf(acc[nbI][mb][1], 0.f);
            sm[SA2+(row+8)*A1S+col]   = fmaxf(acc[nbI][mb][2], 0.f);
            sm[SA2+(row+8)*A1S+col+1] = fmaxf(acc[nbI][mb][3], 0.f);
        }
    }
    __syncthreads();

    // ---------- stage 2 ----------
    float ac2[2][4][4];
    #pragma unroll
    for (int nbI = 0; nbI < 2; nbI++){
        int nb = warp + nbI*8;
        float i0 = d_b2d[nb*8+2*tig], i1 = d_b2d[nb*8+2*tig+1];
        #pragma unroll
        for (int mb = 0; mb < 4; mb++){
            ac2[nbI][mb][0]=i0; ac2[nbI][mb][1]=i1; ac2[nbI][mb][2]=i0; ac2[nbI][mb][3]=i1;
        }
    }
    #pragma unroll 4
    for (int ks = 0; ks < 32; ks++){
        uint32_t af[4][4];
        #pragma unroll
        for (int mb = 0; mb < 4; mb++){
            const float* ap = sm + SA2 + (mb*16+gid)*A1S + ks*8 + tig;
            af[mb][0]=__float_as_uint(ap[0]);   af[mb][1]=__float_as_uint(ap[8*A1S]);
            af[mb][2]=__float_as_uint(ap[4]);   af[mb][3]=__float_as_uint(ap[8*A1S+4]);
        }
        #pragma unroll
        for (int nbI = 0; nbI < 2; nbI++){
            float2 bf = __ldg((const float2*)(d_W2p + (ks*16 + warp + nbI*8)*64 + lane*2));
            #pragma unroll
            for (int mb = 0; mb < 4; mb++) mma8(ac2[nbI][mb], af[mb], bf);
        }
    }
    __syncthreads();
    #pragma unroll
    for (int nbI = 0; nbI < 2; nbI++){
        int col = (warp + nbI*8)*8 + 2*tig;
        #pragma unroll
        for (int mb = 0; mb < 4; mb++){
            int row = mb*16 + gid;
            sm[SA3+row*A3S+col]       = ac2[nbI][mb][0];
            sm[SA3+row*A3S+col+1]     = ac2[nbI][mb][1];
            sm[SA3+(row+8)*A3S+col]   = ac2[nbI][mb][2];
            sm[SA3+(row+8)*A3S+col+1] = ac2[nbI][mb][3];
        }
    }
    __syncthreads();

    // ---------- tension + softmax partials ----------
    if (t < 64){
        const float* o = sm + SA3 + t*A3S;
        float s2 = 0.f;
        for (int j = 0; j < 128; j++){ float v = o[j]; s2 = fmaf(v, v, s2); }
        s2 *= (1.0f/128.0f);
        sm[ST+t] = s2;
        sm[SE+t] = expf(s2);
        sm[SA3+t*A3S+128] = s2;
    }
    __syncthreads();
    if (t < 128){
        float s2 = 0.f;
        for (int c = 0; c < 64; c++) s2 = fmaf(sm[SE+c], sm[SA3+c*A3S+t], s2);
        d_pexpout[b*128+t] = s2;
    } else if (t == 128){
        float s2 = 0.f; for (int c = 0; c < 64; c++) s2 += sm[SE+c];
        d_pexpsum[b] = s2;
    } else if (t == 129){
        float s2 = 0.f; for (int c = 0; c < 64; c++) s2 += sm[ST+c];
        d_ptsum[b] = s2;
    }

    // ---------- GRU: fused 4-gate GEMM, 4 d-slices ----------
    for (int s = 0; s < 4; s++){
        float aR[4][4]={}, aZ[4][4]={}, aI[4][4]={}, aH[4][4]={};
        #pragma unroll 1
        for (int ks = 0; ks < 49; ks++){
            uint32_t af[4][4];
            if (ks < 17){
                #pragma unroll
                for (int mb = 0; mb < 4; mb++){
                    const float* ap = sm + SA3 + (mb*16+gid)*A3S + ks*8 + tig;
                    af[mb][0]=__float_as_uint(ap[0]);   af[mb][1]=__float_as_uint(ap[8*A3S]);
                    af[mb][2]=__float_as_uint(ap[4]);   af[mb][3]=__float_as_uint(ap[8*A3S+4]);
                }
            } else {
                #pragma unroll
                for (int mb = 0; mb < 4; mb++){
                    const float* ap = sm + SA1 + (mb*16+gid)*A1S + (ks*8-136) + tig;
                    af[mb][0]=__float_as_uint(ap[0]);   af[mb][1]=__float_as_uint(ap[8*A1S]);
                    af[mb][2]=__float_as_uint(ap[4]);   af[mb][3]=__float_as_uint(ap[8*A1S+4]);
                }
            }
            const float* wb = d_Wgp + (size_t)((s*49+ks)*4)*512 + warp*64 + lane*2;
            float2 bR = __ldg((const float2*)(wb));
            float2 bZ = __ldg((const float2*)(wb+512));
            #pragma unroll
            for (int mb = 0; mb < 4; mb++){ mma8(aR[mb], af[mb], bR); mma8(aZ[mb], af[mb], bZ); }
            if (ks <= 16){
                float2 bI = __ldg((const float2*)(wb+1024));
                #pragma unroll
                for (int mb = 0; mb < 4; mb++) mma8(aI[mb], af[mb], bI);
            }
            if (ks >= 16){
                float2 bH = __ldg((const float2*)(wb+1536));
                #pragma unroll
                for (int mb = 0; mb < 4; mb++) mma8(aH[mb], af[mb], bH);
            }
        }
        int d0 = s*64 + warp*8 + 2*tig;
        #pragma unroll
        for (int mb = 0; mb < 4; mb++){
            #pragma unroll
            for (int hf = 0; hf < 2; hf++){
                int row = mb*16 + gid + hf*8;
                int cell = cell0 + row;
                float2 hh = *(const float2*)(hiddens + (size_t)cell*256 + d0);
                float sc = fmaf(0.02f, sm[SPAY+row], 0.9f);
                #pragma unroll
                for (int q = 0; q < 2; q++){
                    int e = hf*2 + q;
                    float r  = 1.0f/(1.0f + expf(-aR[mb][e]));
                    float z  = 1.0f/(1.0f + expf(-aZ[mb][e]));
                    float nn = tanhf(fmaf(r, aH[mb][e], aI[mb][e]));
                    float h  = q ? hh.y : hh.x;
                    float v  = (1.0f - z)*nn + z*h;
                    v *= sc;
                    v = fminf(10.0f, fmaxf(-10.0f, v));
                    d_hp[(size_t)cell*256 + d0 + q] = v;
                    sm[SA2 + row*A1S + d0 + q] = v;
                }
            }
        }
    }
    __syncthreads();
    {
        float ssum = 0.f;
        for (int c = 0; c < 64; c++) ssum += sm[SA2 + c*A1S + t];
        d_pfsum[b*256 + t] = ssum;
    }
}

// ================= kB1: deterministic reductions =================
__global__ void kB1() {
    int tid = blockIdx.x*blockDim.x + threadIdx.x;
    if (tid < 2048){
        int f = tid>>8, d = tid&255;
        float S = 0.f, D = 0.f;
        const float* p = d_pfsum + (size_t)(f*256)*256 + d;
        for (int b2 = 0; b2 < 256; b2++){
            float v = p[(size_t)b2*256];
            S += v;
            if (b2 < 64) D += v;   // first 4096 cells of faction = first 64 blocks
        }
        d_Sf[tid] = S; d_Df[tid] = D;
    } else if (tid < 2176){
        int j = tid - 2048; float s = 0.f;
        for (int b2 = 0; b2 < NBLK; b2++) s += d_pexpout[b2*128+j];
        d_eor[j] = s;
    } else if (tid == 2176){
        float s = 0.f; for (int b2 = 0; b2 < NBLK; b2++) s += d_pexpsum[b2];
        d_es = s;
    } else if (tid == 2177){
        float s = 0.f; for (int b2 = 0; b2 < NBLK; b2++) s += d_ptsum[b2];
        d_ts = s;
    }
}

// ================= kB2: stats + pred + avg_tension =================
__global__ void kB2(const float* __restrict__ head_w, const float* __restrict__ head_b,
                    const int* __restrict__ stepp, float* __restrict__ out) {
    int t = threadIdx.x;
    int step = *stepp;
    if (t < 256){
        float Sfv[8];
        #pragma unroll
        for (int f = 0; f < 8; f++) Sfv[f] = d_Sf[f*256+t];
        float go = 0.f;
        #pragma unroll
        for (int f = 0; f < 8; f++) go += Sfv[f]*(1.0f/16384.0f);
        go *= 0.125f;
        d_go[t] = go;
        float gsum = 0.f;
        #pragma unroll
        for (int f = 0; f < 8; f++){
            float fm = Sfv[f]*(1.0f/16384.0f);
            d_fmean[f*256+t] = fm;
            float Tf = Sfv[f];
            if (step > 5){
                float D = d_Df[f*256+t];
                Tf += 0.15f*(4096.0f*go - 0.85f*D - 4096.0f*0.15f*fm);
            }
            gsum += Tf;
        }
        d_gmean[t] = gsum*(1.0f/131072.0f);
    }
    if (t < 128){
        float inv = 1.0f/d_es;
        float s = head_b[t];
        const float* hw = head_w + t*128;
        for (int j = 0; j < 128; j++) s = fmaf(d_eor[j]*inv, hw[j], s);
        out[t] = s;
    }
    if (t == 0) out[128] = d_ts*(1.0f/131072.0f);
}

// ================= threefry (partitionable) + XLA erf_inv =================
__device__ __forceinline__ uint32_t threefry_bits(uint32_t x0, uint32_t x1) {
    const uint32_t ks0 = 0u, ks1 = 42u, ks2 = 0x1BD11BF0u;
    x0 += ks0; x1 += ks1;
#define RND(R) { x0 += x1; x1 = (x1 << R) | (x1 >> (32 - R)); x1 ^= x0; }
    RND(13) RND(15) RND(26) RND(6)   x0 += ks1; x1 += ks2 + 1u;
    RND(17) RND(29) RND(16) RND(24)  x0 += ks2; x1 += ks0 + 2u;
    RND(13) RND(15) RND(26) RND(6)   x0 += ks0; x1 += ks1 + 3u;
    RND(17) RND(29) RND(16) RND(24)  x0 += ks1; x1 += ks2 + 4u;
    RND(13) RND(15) RND(26) RND(6)   x0 += ks2; x1 += ks0 + 5u;
#undef RND
    return x0 ^ x1;
}
__device__ __forceinline__ float erfinv_xla(float x) {
    float w = -log1pf(-x*x);
    float p;
    if (w < 5.0f){
        w -= 2.5f;
        p = 2.81022636e-08f;
        p = fmaf(p, w, 3.43273939e-07f);  p = fmaf(p, w, -3.5233877e-06f);
        p = fmaf(p, w, -4.39150654e-06f); p = fmaf(p, w, 0.00021858087f);
        p = fmaf(p, w, -0.00125372503f);  p = fmaf(p, w, -0.00417768164f);
        p = fmaf(p, w, 0.246640727f);     p = fmaf(p, w, 1.50140941f);
    } else {
        w = sqrtf(w) - 3.0f;
        p = -0.000200214257f;
        p = fmaf(p, w, 0.000100950558f);  p = fmaf(p, w, 0.00134934322f);
        p = fmaf(p, w, -0.00367342844f);  p = fmaf(p, w, 0.00573950773f);
        p = fmaf(p, w, -0.0076224613f);   p = fmaf(p, w, 0.00943887047f);
        p = fmaf(p, w, 1.00167406f);      p = fmaf(p, w, 2.83297682f);
    }
    return p*x;
}
__device__ __forceinline__ float bits_to_normal(uint32_t bits) {
    float u01 = __uint_as_float((bits >> 9) | 0x3f800000u) - 1.0f;
    float u = u01*2.0f + (-0.99999994f);
    u = fmaxf(-0.99999994f, u);
    return 1.4142135623730951f*erfinv_xla(u);
}

// ================= kC: sync/debate/pull/noise/clamp =================
__global__ void kC(const int* __restrict__ lact, const int* __restrict__ stepp,
                   float* __restrict__ out) {
    const int cell = blockIdx.x;
    const int d = threadIdx.x;
    const int step = *stepp;
    uint32_t m = (uint32_t)cell*256u + (uint32_t)d;
    float n0 = bits_to_normal(threefry_bits(0u, m));
    float n1 = bits_to_normal(threefry_bits(0u, m + 16777216u));
    const float gm = d_gmean[d];
    const float go = d_go[d];
    #pragma unroll
    for (int half = 0; half < 2; half++){
        int c = cell + half*65536;
        float n = half ? n1 : n0;
        float v = d_hp[(size_t)c*256 + d];
        int f = c >> 14;
        v = 0.85f*v + 0.15f*d_fmean[f*256+d];
        if (step > 5 && (c & 16383) < DC) v = 0.85f*v + 0.15f*go;
        float coop = (float)lact[c];
        v += 0.05f*coop*(gm - v);
        v += 0.02f*(1.0f - coop)*n;
        v = fminf(10.0f, fmaxf(-10.0f, v));
        out[129 + (size_t)c*256 + d] = v;
    }
}

// ================= launch =================
extern "C" void kernel_launch(void* const* d_in, const int* in_sizes, int n_in,
                              void* d_out, int out_size) {
    const float* x       = (const float*)d_in[0];
    const float* payoffs = (const float*)d_in[1];
    const int*   last    = (const int*)d_in[2];
    const int*   step    = (const int*)d_in[3];
    const float* hiddens = (const float*)d_in[4];
    const float* a_w1    = (const float*)d_in[5];
    const float* a_b1    = (const float*)d_in[6];
    const float* a_w2    = (const float*)d_in[7];
    const float* a_b2    = (const float*)d_in[8];
    const float* g_w1    = (const float*)d_in[9];
    const float* g_b1    = (const float*)d_in[10];
    const float* g_w2    = (const float*)d_in[11];
    const float* g_b2    = (const float*)d_in[12];
    const float* gru_wih = (const float*)d_in[13];
    const float* gru_whh = (const float*)d_in[14];
    const float* gru_bih = (const float*)d_in[15];
    const float* gru_bhh = (const float*)d_in[16];
    const float* head_w  = (const float*)d_in[17];
    const float* head_b  = (const float*)d_in[18];
    float* out = (float*)d_out;

    cudaFuncSetAttribute(kA, cudaFuncAttributeMaxDynamicSharedMemorySize, SMW*4);

    kPrep<<<512, 256>>>(x, a_w1, a_b1, g_w1, g_b1, a_w2, a_b2, g_w2, g_b2,
                        gru_wih, gru_whh, gru_bih, gru_bhh);
    kA<<<NBLK, 256, SMW*4>>>(hiddens, payoffs);
    kB1<<<18, 128>>>();
    kB2<<<1, 256>>>(head_w, head_b, step, out);
    kC<<<65536, 256>>>(last, step, out);
}

// round 6
// speedup vs baseline: 4.5797x; 1.7416x over previous
#include <cuda_runtime.h>
#include <cstdint>

#define NCELLS 131072
#define MC     64
#define NBLK   (NCELLS/MC)   // 2048
#define DC     4096

// ---------------- device scratch ----------------
__device__ __align__(16) float d_W1p[32*32*64];      // stage1 B frags
__device__ __align__(16) float d_W2p[32*16*64];      // stage2 B frags
__device__ __align__(16) float d_Wgp[4*49*4*8*64];   // GRU B frags
__device__ float d_xa[128], d_xg[128], d_b2d[128];
__device__ float d_hp[NCELLS*256];
__device__ float d_pfsum[NBLK*256];
__device__ float d_pexpout[NBLK*128];
__device__ float d_pexpsum[NBLK], d_ptsum[NBLK];
__device__ float d_Sf[8*256], d_Df[8*256], d_eor[128], d_es, d_ts;
__device__ float d_fmean[8*256], d_go[256], d_gmean[256];

// ---------------- smem layout (float words) ----------------
#define A1S 260
#define A3S 148
#define SA1 0          // h tile 64x260 (also GRU K-tail A)
#define SA2 16640      // [a1|g1] 64x260, reused for new_h
#define SA3 33280      // [out|tension|1|0s] 64x148
#define ST  42752
#define SE  42816
#define SPAY 42880
#define SMW 42944      // words -> 171776 bytes

__device__ __forceinline__ float rna(float x){
    float r; asm("cvt.rna.tf32.f32 %0, %1;" : "=f"(r) : "f"(x)); return r;
}
__device__ __forceinline__ void mma8(float* c, const uint32_t* a, float2 b){
    asm volatile(
        "mma.sync.aligned.m16n8k8.row.col.f32.tf32.tf32.f32 "
        "{%0,%1,%2,%3}, {%4,%5,%6,%7}, {%8,%9}, {%0,%1,%2,%3};"
        : "+f"(c[0]), "+f"(c[1]), "+f"(c[2]), "+f"(c[3])
        : "r"(a[0]), "r"(a[1]), "r"(a[2]), "r"(a[3]),
          "r"(__float_as_uint(b.x)), "r"(__float_as_uint(b.y)));
}

// ================= kPrep: permute weights into B-fragment layout =================
__global__ void kPrep(const float* __restrict__ x,
                      const float* __restrict__ aw1, const float* __restrict__ ab1,
                      const float* __restrict__ gw1, const float* __restrict__ gb1,
                      const float* __restrict__ aw2, const float* __restrict__ ab2,
                      const float* __restrict__ gw2, const float* __restrict__ gb2,
                      const float* __restrict__ wih, const float* __restrict__ whh,
                      const float* __restrict__ bih, const float* __restrict__ bhh) {
    int tid = blockIdx.x*blockDim.x + threadIdx.x;
    int nth = gridDim.x*blockDim.x;
    for (int i = tid; i < 32*32*64; i += nth){
        int q=i&1, l=(i>>1)&31, nb=(i>>6)&31, ks=i>>11;
        int j=(nb&15)*8+(l>>2), k=ks*8+(l&3)+q*4;
        const float* w = (nb<16)? aw1 : gw1;
        d_W1p[i] = rna(w[j*384 + 128 + k]);
    }
    for (int i = tid; i < 32*16*64; i += nth){
        int q=i&1, l=(i>>1)&31, nb=(i>>6)&15, ks=i>>10;
        int j=nb*8+(l>>2), k=ks*8+(l&3)+q*4;
        float v = (k<128)? aw2[j*128+k] : -gw2[j*128+(k-128)];
        d_W2p[i] = rna(v);
    }
    // GRU: K=[out 0..127 | tension 128 | ones 129 | 0 130..135 | h 136..391]
    for (int i = tid; i < 4*49*4*8*64; i += nth){
        int q=i&1, l=(i>>1)&31, w8=(i>>6)&7, g=(i>>9)&3, rest=i>>11;
        int ks=rest%49, slice=rest/49;
        int d=(slice*8+w8)*8+(l>>2);
        int k=ks*8+(l&3)+q*4;
        float v = 0.f;
        if (g==0){
            if (k<129) v = wih[d*129+k];
            else if (k==129) v = bih[d]+bhh[d];
            else if (k>=136) v = whh[d*256+k-136];
        } else if (g==1){
            int r = 256+d;
            if (k<129) v = wih[r*129+k];
            else if (k==129) v = bih[r]+bhh[r];
            else if (k>=136) v = whh[r*256+k-136];
        } else if (g==2){
            int r = 512+d;
            if (k<129) v = wih[r*129+k];
            else if (k==129) v = bih[r];
        } else {
            int r = 512+d;
            if (k==129) v = bhh[r];
            else if (k>=136) v = whh[r*256+k-136];
        }
        d_Wgp[i] = rna(v);
    }
    if (tid < 128){
        d_b2d[tid] = ab2[tid] - gb2[tid];
        float s = ab1[tid];
        const float* w = aw1 + tid*384;
        for (int k = 0; k < 128; k++) s = fmaf(x[k], w[k], s);
        d_xa[tid] = s;
        s = gb1[tid];
        w = gw1 + tid*384;
        for (int k = 0; k < 128; k++) s = fmaf(x[k], w[k], s);
        d_xg[tid] = s;
    }
}

// ================= kA: tensor-core fused pipeline (pipelined loads) =================
__global__ __launch_bounds__(256,1)
void kA(const float* __restrict__ hiddens, const float* __restrict__ payoffs){
    extern __shared__ float sm[];
    const int t = threadIdx.x, b = blockIdx.x, cell0 = b*MC;
    const int warp = t>>5, lane = t&31, gid = lane>>2, tig = lane&3;

    for (int e = t; e < 64*64; e += 256){
        int row = e>>6, c4 = e&63;
        float4 v = ((const float4*)hiddens)[(size_t)(cell0+row)*64 + c4];
        *(float4*)(sm + SA1 + row*A1S + c4*4) = v;
    }
    if (t < 64){
        sm[SPAY+t] = payoffs[cell0+t];
        float* r3 = sm + SA3 + t*A3S;
        r3[129] = 1.f;
        #pragma unroll
        for (int c = 130; c < 136; c++) r3[c] = 0.f;
    }
    __syncthreads();

    // ---------- stage 1 ----------
    float acc[4][4][4];
    #pragma unroll
    for (int nbI = 0; nbI < 4; nbI++){
        int nb = warp + nbI*8;
        const float* xv = ((nb<16)? d_xa : d_xg) + (nb&15)*8 + 2*tig;
        float i0 = xv[0], i1 = xv[1];
        #pragma unroll
        for (int mb = 0; mb < 4; mb++){
            acc[nbI][mb][0]=i0; acc[nbI][mb][1]=i1; acc[nbI][mb][2]=i0; acc[nbI][mb][3]=i1;
        }
    }
    {
        float2 bf[4];
        #pragma unroll
        for (int nbI = 0; nbI < 4; nbI++)
            bf[nbI] = __ldg((const float2*)(d_W1p + (warp + nbI*8)*64 + lane*2));
        #pragma unroll 4
        for (int ks = 0; ks < 32; ks++){
            float2 bn[4];
            if (ks < 31){
                #pragma unroll
                for (int nbI = 0; nbI < 4; nbI++)
                    bn[nbI] = __ldg((const float2*)(d_W1p + ((ks+1)*32 + warp + nbI*8)*64 + lane*2));
            }
            uint32_t af[4][4];
            #pragma unroll
            for (int mb = 0; mb < 4; mb++){
                const float* ap = sm + SA1 + (mb*16+gid)*A1S + ks*8 + tig;
                af[mb][0]=__float_as_uint(ap[0]);   af[mb][1]=__float_as_uint(ap[8*A1S]);
                af[mb][2]=__float_as_uint(ap[4]);   af[mb][3]=__float_as_uint(ap[8*A1S+4]);
            }
            #pragma unroll
            for (int nbI = 0; nbI < 4; nbI++)
                #pragma unroll
                for (int mb = 0; mb < 4; mb++) mma8(acc[nbI][mb], af[mb], bf[nbI]);
            #pragma unroll
            for (int nbI = 0; nbI < 4; nbI++) bf[nbI] = bn[nbI];
        }
    }
    __syncthreads();
    #pragma unroll
    for (int nbI = 0; nbI < 4; nbI++){
        int col = (warp + nbI*8)*8 + 2*tig;
        #pragma unroll
        for (int mb = 0; mb < 4; mb++){
            int row = mb*16 + gid;
            sm[SA2+row*A1S+col]       = fmaxf(acc[nbI][mb][0], 0.f);
            sm[SA2+row*A1S+col+1]     = fmaxf(acc[nbI][mb][1], 0.f);
            sm[SA2+(row+8)*A1S+col]   = fmaxf(acc[nbI][mb][2], 0.f);
            sm[SA2+(row+8)*A1S+col+1] = fmaxf(acc[nbI][mb][3], 0.f);
        }
    }
    __syncthreads();

    // ---------- stage 2 ----------
    float ac2[2][4][4];
    #pragma unroll
    for (int nbI = 0; nbI < 2; nbI++){
        int nb = warp + nbI*8;
        float i0 = d_b2d[nb*8+2*tig], i1 = d_b2d[nb*8+2*tig+1];
        #pragma unroll
        for (int mb = 0; mb < 4; mb++){
            ac2[nbI][mb][0]=i0; ac2[nbI][mb][1]=i1; ac2[nbI][mb][2]=i0; ac2[nbI][mb][3]=i1;
        }
    }
    {
        float2 bf[2];
        #pragma unroll
        for (int nbI = 0; nbI < 2; nbI++)
            bf[nbI] = __ldg((const float2*)(d_W2p + (warp + nbI*8)*64 + lane*2));
        #pragma unroll 4
        for (int ks = 0; ks < 32; ks++){
            float2 bn[2];
            if (ks < 31){
                #pragma unroll
                for (int nbI = 0; nbI < 2; nbI++)
                    bn[nbI] = __ldg((const float2*)(d_W2p + ((ks+1)*16 + warp + nbI*8)*64 + lane*2));
            }
            uint32_t af[4][4];
            #pragma unroll
            for (int mb = 0; mb < 4; mb++){
                const float* ap = sm + SA2 + (mb*16+gid)*A1S + ks*8 + tig;
                af[mb][0]=__float_as_uint(ap[0]);   af[mb][1]=__float_as_uint(ap[8*A1S]);
                af[mb][2]=__float_as_uint(ap[4]);   af[mb][3]=__float_as_uint(ap[8*A1S+4]);
            }
            #pragma unroll
            for (int nbI = 0; nbI < 2; nbI++)
                #pragma unroll
                for (int mb = 0; mb < 4; mb++) mma8(ac2[nbI][mb], af[mb], bf[nbI]);
            #pragma unroll
            for (int nbI = 0; nbI < 2; nbI++) bf[nbI] = bn[nbI];
        }
    }
    __syncthreads();
    #pragma unroll
    for (int nbI = 0; nbI < 2; nbI++){
        int col = (warp + nbI*8)*8 + 2*tig;
        #pragma unroll
        for (int mb = 0; mb < 4; mb++){
            int row = mb*16 + gid;
            sm[SA3+row*A3S+col]       = ac2[nbI][mb][0];
            sm[SA3+row*A3S+col+1]     = ac2[nbI][mb][1];
            sm[SA3+(row+8)*A3S+col]   = ac2[nbI][mb][2];
            sm[SA3+(row+8)*A3S+col+1] = ac2[nbI][mb][3];
        }
    }
    __syncthreads();

    // ---------- tension + softmax partials ----------
    if (t < 64){
        const float* o = sm + SA3 + t*A3S;
        float s2 = 0.f;
        for (int j = 0; j < 128; j++){ float v = o[j]; s2 = fmaf(v, v, s2); }
        s2 *= (1.0f/128.0f);
        sm[ST+t] = s2;
        sm[SE+t] = expf(s2);
        sm[SA3+t*A3S+128] = s2;
    }
    __syncthreads();
    if (t < 128){
        float s2 = 0.f;
        for (int c = 0; c < 64; c++) s2 = fmaf(sm[SE+c], sm[SA3+c*A3S+t], s2);
        d_pexpout[b*128+t] = s2;
    } else if (t == 128){
        float s2 = 0.f; for (int c = 0; c < 64; c++) s2 += sm[SE+c];
        d_pexpsum[b] = s2;
    } else if (t == 129){
        float s2 = 0.f; for (int c = 0; c < 64; c++) s2 += sm[ST+c];
        d_ptsum[b] = s2;
    }

    // ---------- GRU: fused 4-gate GEMM, 4 d-slices, pipelined ----------
    for (int s = 0; s < 4; s++){
        const float* wb0 = d_Wgp + (size_t)((s*49)*4)*512 + warp*64 + lane*2;
        float aR[4][4]={}, aZ[4][4]={}, aI[4][4]={}, aH[4][4]={};

        // ---- phase 1: ks 0..16, gates R,Z,I (A from out-tile SA3) ----
        float2 bR = __ldg((const float2*)(wb0));
        float2 bZ = __ldg((const float2*)(wb0+512));
        float2 bI = __ldg((const float2*)(wb0+1024));
        uint32_t af[4][4];
        #pragma unroll
        for (int mb = 0; mb < 4; mb++){
            const float* ap = sm + SA3 + (mb*16+gid)*A3S + tig;
            af[mb][0]=__float_as_uint(ap[0]);   af[mb][1]=__float_as_uint(ap[8*A3S]);
            af[mb][2]=__float_as_uint(ap[4]);   af[mb][3]=__float_as_uint(ap[8*A3S+4]);
        }
        #pragma unroll 4
        for (int ks = 0; ks < 17; ks++){
            float2 bRn, bZn, bIn;
            uint32_t afn[4][4];
            if (ks < 16){
                const float* wn = wb0 + (ks+1)*2048;
                bRn = __ldg((const float2*)(wn));
                bZn = __ldg((const float2*)(wn+512));
                bIn = __ldg((const float2*)(wn+1024));
                #pragma unroll
                for (int mb = 0; mb < 4; mb++){
                    const float* ap = sm + SA3 + (mb*16+gid)*A3S + (ks+1)*8 + tig;
                    afn[mb][0]=__float_as_uint(ap[0]);   afn[mb][1]=__float_as_uint(ap[8*A3S]);
                    afn[mb][2]=__float_as_uint(ap[4]);   afn[mb][3]=__float_as_uint(ap[8*A3S+4]);
                }
            }
            #pragma unroll
            for (int mb = 0; mb < 4; mb++){
                mma8(aR[mb], af[mb], bR);
                mma8(aZ[mb], af[mb], bZ);
                mma8(aI[mb], af[mb], bI);
            }
            if (ks == 16){
                float2 bH16 = __ldg((const float2*)(wb0 + 16*2048 + 1536));
                #pragma unroll
                for (int mb = 0; mb < 4; mb++) mma8(aH[mb], af[mb], bH16);
            }
            bR = bRn; bZ = bZn; bI = bIn;
            #pragma unroll
            for (int mb = 0; mb < 4; mb++)
                #pragma unroll
                for (int e2 = 0; e2 < 4; e2++) af[mb][e2] = afn[mb][e2];
        }

        // ---- phase 2: ks 17..48, gates R,Z,H (A from h-tile SA1) ----
        {
            const float* w17 = wb0 + 17*2048;
            bR = __ldg((const float2*)(w17));
            bZ = __ldg((const float2*)(w17+512));
        }
        float2 bH = __ldg((const float2*)(wb0 + 17*2048 + 1536));
        #pragma unroll
        for (int mb = 0; mb < 4; mb++){
            const float* ap = sm + SA1 + (mb*16+gid)*A1S + (17*8-136) + tig;
            af[mb][0]=__float_as_uint(ap[0]);   af[mb][1]=__float_as_uint(ap[8*A1S]);
            af[mb][2]=__float_as_uint(ap[4]);   af[mb][3]=__float_as_uint(ap[8*A1S+4]);
        }
        #pragma unroll 4
        for (int ks = 17; ks < 49; ks++){
            float2 bRn, bZn, bHn;
            uint32_t afn[4][4];
            if (ks < 48){
                const float* wn = wb0 + (ks+1)*2048;
                bRn = __ldg((const float2*)(wn));
                bZn = __ldg((const float2*)(wn+512));
                bHn = __ldg((const float2*)(wn+1536));
                #pragma unroll
                for (int mb = 0; mb < 4; mb++){
                    const float* ap = sm + SA1 + (mb*16+gid)*A1S + ((ks+1)*8-136) + tig;
                    afn[mb][0]=__float_as_uint(ap[0]);   afn[mb][1]=__float_as_uint(ap[8*A1S]);
                    afn[mb][2]=__float_as_uint(ap[4]);   afn[mb][3]=__float_as_uint(ap[8*A1S+4]);
                }
            }
            #pragma unroll
            for (int mb = 0; mb < 4; mb++){
                mma8(aR[mb], af[mb], bR);
                mma8(aZ[mb], af[mb], bZ);
                mma8(aH[mb], af[mb], bH);
            }
            bR = bRn; bZ = bZn; bH = bHn;
            #pragma unroll
            for (int mb = 0; mb < 4; mb++)
                #pragma unroll
                for (int e2 = 0; e2 < 4; e2++) af[mb][e2] = afn[mb][e2];
        }

        // ---- epilogue: gates + payoff + clamp ----
        int d0 = s*64 + warp*8 + 2*tig;
        #pragma unroll
        for (int mb = 0; mb < 4; mb++){
            #pragma unroll
            for (int hf = 0; hf < 2; hf++){
                int row = mb*16 + gid + hf*8;
                int cell = cell0 + row;
                float2 hh = *(const float2*)(hiddens + (size_t)cell*256 + d0);
                float sc = fmaf(0.02f, sm[SPAY+row], 0.9f);
                #pragma unroll
                for (int q = 0; q < 2; q++){
                    int e = hf*2 + q;
                    float r  = 1.0f/(1.0f + expf(-aR[mb][e]));
                    float z  = 1.0f/(1.0f + expf(-aZ[mb][e]));
                    float nn = tanhf(fmaf(r, aH[mb][e], aI[mb][e]));
                    float h  = q ? hh.y : hh.x;
                    float v  = (1.0f - z)*nn + z*h;
                    v *= sc;
                    v = fminf(10.0f, fmaxf(-10.0f, v));
                    d_hp[(size_t)cell*256 + d0 + q] = v;
                    sm[SA2 + row*A1S + d0 + q] = v;
                }
            }
        }
    }
    __syncthreads();
    {
        float ssum = 0.f;
        for (int c = 0; c < 64; c++) ssum += sm[SA2 + c*A1S + t];
        d_pfsum[b*256 + t] = ssum;
    }
}

// ================= kB1: deterministic reductions =================
__global__ void kB1() {
    int tid = blockIdx.x*blockDim.x + threadIdx.x;
    if (tid < 2048){
        int f = tid>>8, d = tid&255;
        float S = 0.f, D = 0.f;
        const float* p = d_pfsum + (size_t)(f*256)*256 + d;
        for (int b2 = 0; b2 < 256; b2++){
            float v = p[(size_t)b2*256];
            S += v;
            if (b2 < 64) D += v;
        }
        d_Sf[tid] = S; d_Df[tid] = D;
    } else if (tid < 2176){
        int j = tid - 2048; float s = 0.f;
        for (int b2 = 0; b2 < NBLK; b2++) s += d_pexpout[b2*128+j];
        d_eor[j] = s;
    } else if (tid == 2176){
        float s = 0.f; for (int b2 = 0; b2 < NBLK; b2++) s += d_pexpsum[b2];
        d_es = s;
    } else if (tid == 2177){
        float s = 0.f; for (int b2 = 0; b2 < NBLK; b2++) s += d_ptsum[b2];
        d_ts = s;
    }
}

// ================= kB2: stats + pred + avg_tension =================
__global__ void kB2(const float* __restrict__ head_w, const float* __restrict__ head_b,
                    const int* __restrict__ stepp, float* __restrict__ out) {
    int t = threadIdx.x;
    int step = *stepp;
    if (t < 256){
        float Sfv[8];
        #pragma unroll
        for (int f = 0; f < 8; f++) Sfv[f] = d_Sf[f*256+t];
        float go = 0.f;
        #pragma unroll
        for (int f = 0; f < 8; f++) go += Sfv[f]*(1.0f/16384.0f);
        go *= 0.125f;
        d_go[t] = go;
        float gsum = 0.f;
        #pragma unroll
        for (int f = 0; f < 8; f++){
            float fm = Sfv[f]*(1.0f/16384.0f);
            d_fmean[f*256+t] = fm;
            float Tf = Sfv[f];
            if (step > 5){
                float D = d_Df[f*256+t];
                Tf += 0.15f*(4096.0f*go - 0.85f*D - 4096.0f*0.15f*fm);
            }
            gsum += Tf;
        }
        d_gmean[t] = gsum*(1.0f/131072.0f);
    }
    if (t < 128){
        float inv = 1.0f/d_es;
        float s = head_b[t];
        const float* hw = head_w + t*128;
        for (int j = 0; j < 128; j++) s = fmaf(d_eor[j]*inv, hw[j], s);
        out[t] = s;
    }
    if (t == 0) out[128] = d_ts*(1.0f/131072.0f);
}

// ================= threefry (partitionable) + XLA erf_inv =================
__device__ __forceinline__ uint32_t threefry_bits(uint32_t x0, uint32_t x1) {
    const uint32_t ks0 = 0u, ks1 = 42u, ks2 = 0x1BD11BF0u;
    x0 += ks0; x1 += ks1;
#define RND(R) { x0 += x1; x1 = (x1 << R) | (x1 >> (32 - R)); x1 ^= x0; }
    RND(13) RND(15) RND(26) RND(6)   x0 += ks1; x1 += ks2 + 1u;
    RND(17) RND(29) RND(16) RND(24)  x0 += ks2; x1 += ks0 + 2u;
    RND(13) RND(15) RND(26) RND(6)   x0 += ks0; x1 += ks1 + 3u;
    RND(17) RND(29) RND(16) RND(24)  x0 += ks1; x1 += ks2 + 4u;
    RND(13) RND(15) RND(26) RND(6)   x0 += ks2; x1 += ks0 + 5u;
#undef RND
    return x0 ^ x1;
}
__device__ __forceinline__ float erfinv_xla(float x) {
    float w = -log1pf(-x*x);
    float p;
    if (w < 5.0f){
        w -= 2.5f;
        p = 2.81022636e-08f;
        p = fmaf(p, w, 3.43273939e-07f);  p = fmaf(p, w, -3.5233877e-06f);
        p = fmaf(p, w, -4.39150654e-06f); p = fmaf(p, w, 0.00021858087f);
        p = fmaf(p, w, -0.00125372503f);  p = fmaf(p, w, -0.00417768164f);
        p = fmaf(p, w, 0.246640727f);     p = fmaf(p, w, 1.50140941f);
    } else {
        w = sqrtf(w) - 3.0f;
        p = -0.000200214257f;
        p = fmaf(p, w, 0.000100950558f);  p = fmaf(p, w, 0.00134934322f);
        p = fmaf(p, w, -0.00367342844f);  p = fmaf(p, w, 0.00573950773f);
        p = fmaf(p, w, -0.0076224613f);   p = fmaf(p, w, 0.00943887047f);
        p = fmaf(p, w, 1.00167406f);      p = fmaf(p, w, 2.83297682f);
    }
    return p*x;
}
__device__ __forceinline__ float bits_to_normal(uint32_t bits) {
    float u01 = __uint_as_float((bits >> 9) | 0x3f800000u) - 1.0f;
    float u = u01*2.0f + (-0.99999994f);
    u = fmaxf(-0.99999994f, u);
    return 1.4142135623730951f*erfinv_xla(u);
}

// ================= kC: sync/debate/pull/noise/clamp =================
__global__ void kC(const int* __restrict__ lact, const int* __restrict__ stepp,
                   float* __restrict__ out) {
    const int cell = blockIdx.x;
    const int d = threadIdx.x;
    const int step = *stepp;
    uint32_t m = (uint32_t)cell*256u + (uint32_t)d;
    float n0 = bits_to_normal(threefry_bits(0u, m));
    float n1 = bits_to_normal(threefry_bits(0u, m + 16777216u));
    const float gm = d_gmean[d];
    const float go = d_go[d];
    #pragma unroll
    for (int half = 0; half < 2; half++){
        int c = cell + half*65536;
        float n = half ? n1 : n0;
        float v = d_hp[(size_t)c*256 + d];
        int f = c >> 14;
        v = 0.85f*v + 0.15f*d_fmean[f*256+d];
        if (step > 5 && (c & 16383) < DC) v = 0.85f*v + 0.15f*go;
        float coop = (float)lact[c];
        v += 0.05f*coop*(gm - v);
        v += 0.02f*(1.0f - coop)*n;
        v = fminf(10.0f, fmaxf(-10.0f, v));
        out[129 + (size_t)c*256 + d] = v;
    }
}

// ================= launch =================
extern "C" void kernel_launch(void* const* d_in, const int* in_sizes, int n_in,
                              void* d_out, int out_size) {
    const float* x       = (const float*)d_in[0];
    const float* payoffs = (const float*)d_in[1];
    const int*   last    = (const int*)d_in[2];
    const int*   step    = (const int*)d_in[3];
    const float* hiddens = (const float*)d_in[4];
    const float* a_w1    = (const float*)d_in[5];
    const float* a_b1    = (const float*)d_in[6];
    const float* a_w2    = (const float*)d_in[7];
    const float* a_b2    = (const float*)d_in[8];
    const float* g_w1    = (const float*)d_in[9];
    const float* g_b1    = (const float*)d_in[10];
    const float* g_w2    = (const float*)d_in[11];
    const float* g_b2    = (const float*)d_in[12];
    const float* gru_wih = (const float*)d_in[13];
    const float* gru_whh = (const float*)d_in[14];
    const float* gru_bih = (const float*)d_in[15];
    const float* gru_bhh = (const float*)d_in[16];
    const float* head_w  = (const float*)d_in[17];
    const float* head_b  = (const float*)d_in[18];
    float* out = (float*)d_out;

    cudaFuncSetAttribute(kA, cudaFuncAttributeMaxDynamicSharedMemorySize, SMW*4);

    kPrep<<<512, 256>>>(x, a_w1, a_b1, g_w1, g_b1, a_w2, a_b2, g_w2, g_b2,
                        gru_wih, gru_whh, gru_bih, gru_bhh);
    kA<<<NBLK, 256, SMW*4>>>(hiddens, payoffs);
    kB1<<<18, 128>>>();
    kB2<<<1, 256>>>(head_w, head_b, step, out);
    kC<<<65536, 256>>>(last, step, out);
}

// round 7
// speedup vs baseline: 4.8014x; 1.0484x over previous
#include <cuda_runtime.h>
#include <cstdint>

#define NCELLS 131072
#define MC     64
#define NBLK   (NCELLS/MC)   // 2048
#define DC     4096

// ---------------- device scratch ----------------
__device__ __align__(16) float d_W1p[32*32*64];      // stage1 B frags
__device__ __align__(16) float d_W2p[32*16*64];      // stage2 B frags
__device__ __align__(16) float d_Wgp[4*49*4*8*64];   // GRU B frags
__device__ float d_xa[128], d_xg[128], d_b2d[128];
__device__ float d_hp[NCELLS*256];
__device__ float d_pfsum[NBLK*256];
__device__ float d_pexpout[NBLK*128];
__device__ float d_pexpsum[NBLK], d_ptsum[NBLK];
__device__ float d_Sf[8*256], d_Df[8*256], d_eor[128], d_es, d_ts;
__device__ float d_fmean[8*256], d_go[256], d_gmean[256];

// ---------------- smem layout (float words) ----------------
#define A1S 260
#define A3S 148
#define SA1 0          // h tile 64x260 (also GRU K-tail A)
#define SA2 16640      // [a1|g1] 64x260, reused for new_h
#define SA3 33280      // [out|tension|1|0s] 64x148; reused as reduce scratch
#define ST  42752
#define SE  42816
#define SPAY 42880
#define SMW 42944      // words -> 171776 bytes

__device__ __forceinline__ float rna(float x){
    float r; asm("cvt.rna.tf32.f32 %0, %1;" : "=f"(r) : "f"(x)); return r;
}
__device__ __forceinline__ void mma8(float* c, const uint32_t* a, float2 b){
    asm volatile(
        "mma.sync.aligned.m16n8k8.row.col.f32.tf32.tf32.f32 "
        "{%0,%1,%2,%3}, {%4,%5,%6,%7}, {%8,%9}, {%0,%1,%2,%3};"
        : "+f"(c[0]), "+f"(c[1]), "+f"(c[2]), "+f"(c[3])
        : "r"(a[0]), "r"(a[1]), "r"(a[2]), "r"(a[3]),
          "r"(__float_as_uint(b.x)), "r"(__float_as_uint(b.y)));
}

// ================= kPrep: permute weights into B-fragment layout =================
__global__ void kPrep(const float* __restrict__ x,
                      const float* __restrict__ aw1, const float* __restrict__ ab1,
                      const float* __restrict__ gw1, const float* __restrict__ gb1,
                      const float* __restrict__ aw2, const float* __restrict__ ab2,
                      const float* __restrict__ gw2, const float* __restrict__ gb2,
                      const float* __restrict__ wih, const float* __restrict__ whh,
                      const float* __restrict__ bih, const float* __restrict__ bhh) {
    int tid = blockIdx.x*blockDim.x + threadIdx.x;
    int nth = gridDim.x*blockDim.x;
    for (int i = tid; i < 32*32*64; i += nth){
        int q=i&1, l=(i>>1)&31, nb=(i>>6)&31, ks=i>>11;
        int j=(nb&15)*8+(l>>2), k=ks*8+(l&3)+q*4;
        const float* w = (nb<16)? aw1 : gw1;
        d_W1p[i] = rna(w[j*384 + 128 + k]);
    }
    for (int i = tid; i < 32*16*64; i += nth){
        int q=i&1, l=(i>>1)&31, nb=(i>>6)&15, ks=i>>10;
        int j=nb*8+(l>>2), k=ks*8+(l&3)+q*4;
        float v = (k<128)? aw2[j*128+k] : -gw2[j*128+(k-128)];
        d_W2p[i] = rna(v);
    }
    // GRU: K=[out 0..127 | tension 128 | ones 129 | 0 130..135 | h 136..391]
    for (int i = tid; i < 4*49*4*8*64; i += nth){
        int q=i&1, l=(i>>1)&31, w8=(i>>6)&7, g=(i>>9)&3, rest=i>>11;
        int ks=rest%49, slice=rest/49;
        int d=(slice*8+w8)*8+(l>>2);
        int k=ks*8+(l&3)+q*4;
        float v = 0.f;
        if (g==0){
            if (k<129) v = wih[d*129+k];
            else if (k==129) v = bih[d]+bhh[d];
            else if (k>=136) v = whh[d*256+k-136];
        } else if (g==1){
            int r = 256+d;
            if (k<129) v = wih[r*129+k];
            else if (k==129) v = bih[r]+bhh[r];
            else if (k>=136) v = whh[r*256+k-136];
        } else if (g==2){
            int r = 512+d;
            if (k<129) v = wih[r*129+k];
            else if (k==129) v = bih[r];
        } else {
            int r = 512+d;
            if (k==129) v = bhh[r];
            else if (k>=136) v = whh[r*256+k-136];
        }
        d_Wgp[i] = rna(v);
    }
    if (tid < 128){
        d_b2d[tid] = ab2[tid] - gb2[tid];
        float s = ab1[tid];
        const float* w = aw1 + tid*384;
        for (int k = 0; k < 128; k++) s = fmaf(x[k], w[k], s);
        d_xa[tid] = s;
        s = gb1[tid];
        w = gw1 + tid*384;
        for (int k = 0; k < 128; k++) s = fmaf(x[k], w[k], s);
        d_xg[tid] = s;
    }
}

// ================= kA: tensor-core fused pipeline, 16 warps =================
__global__ __launch_bounds__(512,1)
void kA(const float* __restrict__ hiddens, const float* __restrict__ payoffs){
    extern __shared__ float sm[];
    const int t = threadIdx.x, b = blockIdx.x, cell0 = b*MC;
    const int warp = t>>5, lane = t&31, gid = lane>>2, tig = lane&3;

    for (int e = t; e < 64*64; e += 512){
        int row = e>>6, c4 = e&63;
        float4 v = ((const float4*)hiddens)[(size_t)(cell0+row)*64 + c4];
        *(float4*)(sm + SA1 + row*A1S + c4*4) = v;
    }
    if (t < 64){
        sm[SPAY+t] = payoffs[cell0+t];
        float* r3 = sm + SA3 + t*A3S;
        r3[129] = 1.f;
        #pragma unroll
        for (int c = 130; c < 136; c++) r3[c] = 0.f;
    }
    __syncthreads();

    // ---------- stage 1: 32 nb-blocks over 16 warps (2 each) ----------
    float acc[2][4][4];
    #pragma unroll
    for (int nbI = 0; nbI < 2; nbI++){
        int nb = warp + nbI*16;
        const float* xv = ((nb<16)? d_xa : d_xg) + (nb&15)*8 + 2*tig;
        float i0 = xv[0], i1 = xv[1];
        #pragma unroll
        for (int mb = 0; mb < 4; mb++){
            acc[nbI][mb][0]=i0; acc[nbI][mb][1]=i1; acc[nbI][mb][2]=i0; acc[nbI][mb][3]=i1;
        }
    }
    {
        float2 bf[2];
        #pragma unroll
        for (int nbI = 0; nbI < 2; nbI++)
            bf[nbI] = __ldg((const float2*)(d_W1p + (warp + nbI*16)*64 + lane*2));
        #pragma unroll 4
        for (int ks = 0; ks < 32; ks++){
            float2 bn[2];
            if (ks < 31){
                #pragma unroll
                for (int nbI = 0; nbI < 2; nbI++)
                    bn[nbI] = __ldg((const float2*)(d_W1p + ((ks+1)*32 + warp + nbI*16)*64 + lane*2));
            }
            uint32_t af[4][4];
            #pragma unroll
            for (int mb = 0; mb < 4; mb++){
                const float* ap = sm + SA1 + (mb*16+gid)*A1S + ks*8 + tig;
                af[mb][0]=__float_as_uint(ap[0]);   af[mb][1]=__float_as_uint(ap[8*A1S]);
                af[mb][2]=__float_as_uint(ap[4]);   af[mb][3]=__float_as_uint(ap[8*A1S+4]);
            }
            #pragma unroll
            for (int nbI = 0; nbI < 2; nbI++)
                #pragma unroll
                for (int mb = 0; mb < 4; mb++) mma8(acc[nbI][mb], af[mb], bf[nbI]);
            #pragma unroll
            for (int nbI = 0; nbI < 2; nbI++) bf[nbI] = bn[nbI];
        }
    }
    __syncthreads();
    #pragma unroll
    for (int nbI = 0; nbI < 2; nbI++){
        int col = (warp + nbI*16)*8 + 2*tig;
        #pragma unroll
        for (int mb = 0; mb < 4; mb++){
            int row = mb*16 + gid;
            sm[SA2+row*A1S+col]       = fmaxf(acc[nbI][mb][0], 0.f);
            sm[SA2+row*A1S+col+1]     = fmaxf(acc[nbI][mb][1], 0.f);
            sm[SA2+(row+8)*A1S+col]   = fmaxf(acc[nbI][mb][2], 0.f);
            sm[SA2+(row+8)*A1S+col+1] = fmaxf(acc[nbI][mb][3], 0.f);
        }
    }
    __syncthreads();

    // ---------- stage 2: 16 nb-blocks, one per warp ----------
    float ac2[4][4];
    {
        float i0 = d_b2d[warp*8+2*tig], i1 = d_b2d[warp*8+2*tig+1];
        #pragma unroll
        for (int mb = 0; mb < 4; mb++){
            ac2[mb][0]=i0; ac2[mb][1]=i1; ac2[mb][2]=i0; ac2[mb][3]=i1;
        }
    }
    {
        float2 bf = __ldg((const float2*)(d_W2p + warp*64 + lane*2));
        #pragma unroll 4
        for (int ks = 0; ks < 32; ks++){
            float2 bn;
            if (ks < 31)
                bn = __ldg((const float2*)(d_W2p + ((ks+1)*16 + warp)*64 + lane*2));
            uint32_t af[4][4];
            #pragma unroll
            for (int mb = 0; mb < 4; mb++){
                const float* ap = sm + SA2 + (mb*16+gid)*A1S + ks*8 + tig;
                af[mb][0]=__float_as_uint(ap[0]);   af[mb][1]=__float_as_uint(ap[8*A1S]);
                af[mb][2]=__float_as_uint(ap[4]);   af[mb][3]=__float_as_uint(ap[8*A1S+4]);
            }
            #pragma unroll
            for (int mb = 0; mb < 4; mb++) mma8(ac2[mb], af[mb], bf);
            bf = bn;
        }
    }
    __syncthreads();
    {
        int col = warp*8 + 2*tig;
        #pragma unroll
        for (int mb = 0; mb < 4; mb++){
            int row = mb*16 + gid;
            sm[SA3+row*A3S+col]       = ac2[mb][0];
            sm[SA3+row*A3S+col+1]     = ac2[mb][1];
            sm[SA3+(row+8)*A3S+col]   = ac2[mb][2];
            sm[SA3+(row+8)*A3S+col+1] = ac2[mb][3];
        }
    }
    __syncthreads();

    // ---------- tension + softmax partials ----------
    if (t < 64){
        const float* o = sm + SA3 + t*A3S;
        float s2 = 0.f;
        for (int j = 0; j < 128; j++){ float v = o[j]; s2 = fmaf(v, v, s2); }
        s2 *= (1.0f/128.0f);
        sm[ST+t] = s2;
        sm[SE+t] = expf(s2);
        sm[SA3+t*A3S+128] = s2;
    }
    __syncthreads();
    if (t < 128){
        float s2 = 0.f;
        for (int c = 0; c < 64; c++) s2 = fmaf(sm[SE+c], sm[SA3+c*A3S+t], s2);
        d_pexpout[b*128+t] = s2;
    } else if (t == 128){
        float s2 = 0.f; for (int c = 0; c < 64; c++) s2 += sm[SE+c];
        d_pexpsum[b] = s2;
    } else if (t == 129){
        float s2 = 0.f; for (int c = 0; c < 64; c++) s2 += sm[ST+c];
        d_ptsum[b] = s2;
    }

    // ---------- GRU: 4 slices; warp-groups 0-7 / 8-15 take 2 slices per pass ----------
    const int sg = warp >> 3, w8 = warp & 7;
    for (int sIt = 0; sIt < 2; sIt++){
        const int s = sIt*2 + sg;
        const float* wb0 = d_Wgp + (size_t)((s*49)*4)*512 + w8*64 + lane*2;
        float aR[4][4]={}, aZ[4][4]={}, aI[4][4]={}, aH[4][4]={};

        // ---- phase 1: ks 0..16, gates R,Z,I (A from out-tile SA3) ----
        float2 bR = __ldg((const float2*)(wb0));
        float2 bZ = __ldg((const float2*)(wb0+512));
        float2 bI = __ldg((const float2*)(wb0+1024));
        uint32_t af[4][4];
        #pragma unroll
        for (int mb = 0; mb < 4; mb++){
            const float* ap = sm + SA3 + (mb*16+gid)*A3S + tig;
            af[mb][0]=__float_as_uint(ap[0]);   af[mb][1]=__float_as_uint(ap[8*A3S]);
            af[mb][2]=__float_as_uint(ap[4]);   af[mb][3]=__float_as_uint(ap[8*A3S+4]);
        }
        #pragma unroll 4
        for (int ks = 0; ks < 17; ks++){
            float2 bRn, bZn, bIn;
            uint32_t afn[4][4];
            if (ks < 16){
                const float* wn = wb0 + (ks+1)*2048;
                bRn = __ldg((const float2*)(wn));
                bZn = __ldg((const float2*)(wn+512));
                bIn = __ldg((const float2*)(wn+1024));
                #pragma unroll
                for (int mb = 0; mb < 4; mb++){
                    const float* ap = sm + SA3 + (mb*16+gid)*A3S + (ks+1)*8 + tig;
                    afn[mb][0]=__float_as_uint(ap[0]);   afn[mb][1]=__float_as_uint(ap[8*A3S]);
                    afn[mb][2]=__float_as_uint(ap[4]);   afn[mb][3]=__float_as_uint(ap[8*A3S+4]);
                }
            }
            #pragma unroll
            for (int mb = 0; mb < 4; mb++){
                mma8(aR[mb], af[mb], bR);
                mma8(aZ[mb], af[mb], bZ);
                mma8(aI[mb], af[mb], bI);
            }
            if (ks == 16){
                float2 bH16 = __ldg((const float2*)(wb0 + 16*2048 + 1536));
                #pragma unroll
                for (int mb = 0; mb < 4; mb++) mma8(aH[mb], af[mb], bH16);
            }
            bR = bRn; bZ = bZn; bI = bIn;
            #pragma unroll
            for (int mb = 0; mb < 4; mb++)
                #pragma unroll
                for (int e2 = 0; e2 < 4; e2++) af[mb][e2] = afn[mb][e2];
        }

        // ---- phase 2: ks 17..48, gates R,Z,H (A from h-tile SA1) ----
        {
            const float* w17 = wb0 + 17*2048;
            bR = __ldg((const float2*)(w17));
            bZ = __ldg((const float2*)(w17+512));
        }
        float2 bH = __ldg((const float2*)(wb0 + 17*2048 + 1536));
        #pragma unroll
        for (int mb = 0; mb < 4; mb++){
            const float* ap = sm + SA1 + (mb*16+gid)*A1S + (17*8-136) + tig;
            af[mb][0]=__float_as_uint(ap[0]);   af[mb][1]=__float_as_uint(ap[8*A1S]);
            af[mb][2]=__float_as_uint(ap[4]);   af[mb][3]=__float_as_uint(ap[8*A1S+4]);
        }
        #pragma unroll 4
        for (int ks = 17; ks < 49; ks++){
            float2 bRn, bZn, bHn;
            uint32_t afn[4][4];
            if (ks < 48){
                const float* wn = wb0 + (ks+1)*2048;
                bRn = __ldg((const float2*)(wn));
                bZn = __ldg((const float2*)(wn+512));
                bHn = __ldg((const float2*)(wn+1536));
                #pragma unroll
                for (int mb = 0; mb < 4; mb++){
                    const float* ap = sm + SA1 + (mb*16+gid)*A1S + ((ks+1)*8-136) + tig;
                    afn[mb][0]=__float_as_uint(ap[0]);   afn[mb][1]=__float_as_uint(ap[8*A1S]);
                    afn[mb][2]=__float_as_uint(ap[4]);   afn[mb][3]=__float_as_uint(ap[8*A1S+4]);
                }
            }
            #pragma unroll
            for (int mb = 0; mb < 4; mb++){
                mma8(aR[mb], af[mb], bR);
                mma8(aZ[mb], af[mb], bZ);
                mma8(aH[mb], af[mb], bH);
            }
            bR = bRn; bZ = bZn; bH = bHn;
            #pragma unroll
            for (int mb = 0; mb < 4; mb++)
                #pragma unroll
                for (int e2 = 0; e2 < 4; e2++) af[mb][e2] = afn[mb][e2];
        }

        // ---- epilogue: gates + payoff + clamp ----
        int d0 = s*64 + w8*8 + 2*tig;
        #pragma unroll
        for (int mb = 0; mb < 4; mb++){
            #pragma unroll
            for (int hf = 0; hf < 2; hf++){
                int row = mb*16 + gid + hf*8;
                int cell = cell0 + row;
                float2 hh = *(const float2*)(hiddens + (size_t)cell*256 + d0);
                float sc = fmaf(0.02f, sm[SPAY+row], 0.9f);
                #pragma unroll
                for (int q = 0; q < 2; q++){
                    int e = hf*2 + q;
                    float r  = 1.0f/(1.0f + expf(-aR[mb][e]));
                    float z  = 1.0f/(1.0f + expf(-aZ[mb][e]));
                    float nn = tanhf(fmaf(r, aH[mb][e], aI[mb][e]));
                    float h  = q ? hh.y : hh.x;
                    float v  = (1.0f - z)*nn + z*h;
                    v *= sc;
                    v = fminf(10.0f, fmaxf(-10.0f, v));
                    d_hp[(size_t)cell*256 + d0 + q] = v;
                    sm[SA2 + row*A1S + d0 + q] = v;
                }
            }
        }
    }
    __syncthreads();
    // per-block faction partial sums: 512 threads -> 2-way tree over cells
    {
        int d = t & 255, half = t >> 8;
        float ssum = 0.f;
        for (int c = half*32; c < half*32 + 32; c++) ssum += sm[SA2 + c*A1S + d];
        sm[SA3 + t] = ssum;
    }
    __syncthreads();
    if (t < 256) d_pfsum[b*256 + t] = sm[SA3 + t] + sm[SA3 + 256 + t];
}

// ================= kB1: deterministic reductions =================
__global__ void kB1() {
    int tid = blockIdx.x*blockDim.x + threadIdx.x;
    if (tid < 2048){
        int f = tid>>8, d = tid&255;
        float S = 0.f, D = 0.f;
        const float* p = d_pfsum + (size_t)(f*256)*256 + d;
        for (int b2 = 0; b2 < 256; b2++){
            float v = p[(size_t)b2*256];
            S += v;
            if (b2 < 64) D += v;
        }
        d_Sf[tid] = S; d_Df[tid] = D;
    } else if (tid < 2176){
        int j = tid - 2048; float s = 0.f;
        for (int b2 = 0; b2 < NBLK; b2++) s += d_pexpout[b2*128+j];
        d_eor[j] = s;
    } else if (tid == 2176){
        float s = 0.f; for (int b2 = 0; b2 < NBLK; b2++) s += d_pexpsum[b2];
        d_es = s;
    } else if (tid == 2177){
        float s = 0.f; for (int b2 = 0; b2 < NBLK; b2++) s += d_ptsum[b2];
        d_ts = s;
    }
}

// ================= kB2: stats + pred + avg_tension =================
__global__ void kB2(const float* __restrict__ head_w, const float* __restrict__ head_b,
                    const int* __restrict__ stepp, float* __restrict__ out) {
    int t = threadIdx.x;
    int step = *stepp;
    if (t < 256){
        float Sfv[8];
        #pragma unroll
        for (int f = 0; f < 8; f++) Sfv[f] = d_Sf[f*256+t];
        float go = 0.f;
        #pragma unroll
        for (int f = 0; f < 8; f++) go += Sfv[f]*(1.0f/16384.0f);
        go *= 0.125f;
        d_go[t] = go;
        float gsum = 0.f;
        #pragma unroll
        for (int f = 0; f < 8; f++){
            float fm = Sfv[f]*(1.0f/16384.0f);
            d_fmean[f*256+t] = fm;
            float Tf = Sfv[f];
            if (step > 5){
                float D = d_Df[f*256+t];
                Tf += 0.15f*(4096.0f*go - 0.85f*D - 4096.0f*0.15f*fm);
            }
            gsum += Tf;
        }
        d_gmean[t] = gsum*(1.0f/131072.0f);
    }
    if (t < 128){
        float inv = 1.0f/d_es;
        float s = head_b[t];
        const float* hw = head_w + t*128;
        for (int j = 0; j < 128; j++) s = fmaf(d_eor[j]*inv, hw[j], s);
        out[t] = s;
    }
    if (t == 0) out[128] = d_ts*(1.0f/131072.0f);
}

// ================= threefry (partitionable) + XLA erf_inv =================
__device__ __forceinline__ uint32_t threefry_bits(uint32_t x0, uint32_t x1) {
    const uint32_t ks0 = 0u, ks1 = 42u, ks2 = 0x1BD11BF0u;
    x0 += ks0; x1 += ks1;
#define RND(R) { x0 += x1; x1 = (x1 << R) | (x1 >> (32 - R)); x1 ^= x0; }
    RND(13) RND(15) RND(26) RND(6)   x0 += ks1; x1 += ks2 + 1u;
    RND(17) RND(29) RND(16) RND(24)  x0 += ks2; x1 += ks0 + 2u;
    RND(13) RND(15) RND(26) RND(6)   x0 += ks0; x1 += ks1 + 3u;
    RND(17) RND(29) RND(16) RND(24)  x0 += ks1; x1 += ks2 + 4u;
    RND(13) RND(15) RND(26) RND(6)   x0 += ks2; x1 += ks0 + 5u;
#undef RND
    return x0 ^ x1;
}
__device__ __forceinline__ float erfinv_xla(float x) {
    float w = -log1pf(-x*x);
    float p;
    if (w < 5.0f){
        w -= 2.5f;
        p = 2.81022636e-08f;
        p = fmaf(p, w, 3.43273939e-07f);  p = fmaf(p, w, -3.5233877e-06f);
        p = fmaf(p, w, -4.39150654e-06f); p = fmaf(p, w, 0.00021858087f);
        p = fmaf(p, w, -0.00125372503f);  p = fmaf(p, w, -0.00417768164f);
        p = fmaf(p, w, 0.246640727f);     p = fmaf(p, w, 1.50140941f);
    } else {
        w = sqrtf(w) - 3.0f;
        p = -0.000200214257f;
        p = fmaf(p, w, 0.000100950558f);  p = fmaf(p, w, 0.00134934322f);
        p = fmaf(p, w, -0.00367342844f);  p = fmaf(p, w, 0.00573950773f);
        p = fmaf(p, w, -0.0076224613f);   p = fmaf(p, w, 0.00943887047f);
        p = fmaf(p, w, 1.00167406f);      p = fmaf(p, w, 2.83297682f);
    }
    return p*x;
}
__device__ __forceinline__ float bits_to_normal(uint32_t bits) {
    float u01 = __uint_as_float((bits >> 9) | 0x3f800000u) - 1.0f;
    float u = u01*2.0f + (-0.99999994f);
    u = fmaxf(-0.99999994f, u);
    return 1.4142135623730951f*erfinv_xla(u);
}

// ================= kC: sync/debate/pull/noise/clamp =================
__global__ void kC(const int* __restrict__ lact, const int* __restrict__ stepp,
                   float* __restrict__ out) {
    const int cell = blockIdx.x;
    const int d = threadIdx.x;
    const int step = *stepp;
    const int l0 = lact[cell];
    const int l1 = lact[cell + 65536];
    uint32_t m = (uint32_t)cell*256u + (uint32_t)d;
    // noise only matters for defectors (coop==0); branch is uniform per block-half
    float n0 = l0 ? 0.f : bits_to_normal(threefry_bits(0u, m));
    float n1 = l1 ? 0.f : bits_to_normal(threefry_bits(0u, m + 16777216u));
    const float gm = d_gmean[d];
    const float go = d_go[d];
    #pragma unroll
    for (int half = 0; half < 2; half++){
        int c = cell + half*65536;
        float n = half ? n1 : n0;
        float coop = (float)(half ? l1 : l0);
        float v = d_hp[(size_t)c*256 + d];
        int f = c >> 14;
        v = 0.85f*v + 0.15f*d_fmean[f*256+d];
        if (step > 5 && (c & 16383) < DC) v = 0.85f*v + 0.15f*go;
        v += 0.05f*coop*(gm - v);
        v += 0.02f*(1.0f - coop)*n;
        v = fminf(10.0f, fmaxf(-10.0f, v));
        out[129 + (size_t)c*256 + d] = v;
    }
}

// ================= launch =================
extern "C" void kernel_launch(void* const* d_in, const int* in_sizes, int n_in,
                              void* d_out, int out_size) {
    const float* x       = (const float*)d_in[0];
    const float* payoffs = (const float*)d_in[1];
    const int*   last    = (const int*)d_in[2];
    const int*   step    = (const int*)d_in[3];
    const float* hiddens = (const float*)d_in[4];
    const float* a_w1    = (const float*)d_in[5];
    const float* a_b1    = (const float*)d_in[6];
    const float* a_w2    = (const float*)d_in[7];
    const float* a_b2    = (const float*)d_in[8];
    const float* g_w1    = (const float*)d_in[9];
    const float* g_b1    = (const float*)d_in[10];
    const float* g_w2    = (const float*)d_in[11];
    const float* g_b2    = (const float*)d_in[12];
    const float* gru_wih = (const float*)d_in[13];
    const float* gru_whh = (const float*)d_in[14];
    const float* gru_bih = (const float*)d_in[15];
    const float* gru_bhh = (const float*)d_in[16];
    const float* head_w  = (const float*)d_in[17];
    const float* head_b  = (const float*)d_in[18];
    float* out = (float*)d_out;

    cudaFuncSetAttribute(kA, cudaFuncAttributeMaxDynamicSharedMemorySize, SMW*4);

    kPrep<<<512, 256>>>(x, a_w1, a_b1, g_w1, g_b1, a_w2, a_b2, g_w2, g_b2,
                        gru_wih, gru_whh, gru_bih, gru_bhh);
    kA<<<NBLK, 512, SMW*4>>>(hiddens, payoffs);
    kB1<<<18, 128>>>();
    kB2<<<1, 256>>>(head_w, head_b, step, out);
    kC<<<65536, 256>>>(last, step, out);
}